// round 9
// baseline (speedup 1.0000x reference)
#include <cuda_runtime.h>
#include <cuda_fp16.h>
#include <cstdint>

// Fused, batch-paired kernel:
// corr[b,n] = (1/16384) * sum_h Eh[n,h] * ( sum_w EwT[n,w] * act[b,h,w] )
// CTA = (n-tile 64, batch pair). EwT and Eh tiles (fp16, smem) are computed
// ONCE per CTA and reused for both batches -> 4x less MUFU per work item.
// GEMM: mma.sync.m16n8k16.f16 (fp32 accum), M=64 N=128 K=128, twice.
// Grid 64x4 = 256 CTAs @ 2/SM = single wave.

#define HDIM 128
#define NPTS 4096

// Rows padded to 272B = 17*16 -> ldmatrix lane addrs conflict-free,
// and Eh epilogue reads land on bank (4*(l>>2)+(l&3)) — a permutation.
#define NSTRIDE  272
#define EW_OFF   0
#define EH_OFF   17408                 // 64*272
#define ACT0_OFF 34816
#define ACT1_OFF 69632                 // +128*272
#define RED_OFF  104448                // +128*272
#define SMEM_REQ 105472                // +4*256

__device__ __forceinline__ uint32_t smem_to_u32(const void* p) {
    uint32_t a;
    asm("{ .reg .u64 t; cvta.to.shared.u64 t, %1; cvt.u32.u64 %0, t; }" : "=r"(a) : "l"(p));
    return a;
}

#define LDSM_X4(r0, r1, r2, r3, addr)                                          \
    asm volatile("ldmatrix.sync.aligned.m8n8.x4.shared.b16 {%0,%1,%2,%3}, [%4];" \
        : "=r"(r0), "=r"(r1), "=r"(r2), "=r"(r3) : "r"(addr))

#define MMA_F16(c, a, b0, b1)                                                  \
    asm volatile("mma.sync.aligned.m16n8k16.row.col.f32.f16.f16.f32 "           \
        "{%0,%1,%2,%3},{%4,%5,%6,%7},{%8,%9},{%0,%1,%2,%3};"                    \
        : "+f"((c)[0]), "+f"((c)[1]), "+f"((c)[2]), "+f"((c)[3])                \
        : "r"((a)[0]), "r"((a)[1]), "r"((a)[2]), "r"((a)[3]), "r"(b0), "r"(b1))

__global__ __launch_bounds__(256) void fused_kernel(
    const float* __restrict__ act,    // [8,128,128]
    const float* __restrict__ mu,     // [4096,2]
    const float* __restrict__ sigma,  // [4096,2]
    float* __restrict__ out)          // [8,4096]
{
    extern __shared__ char smem[];
    const uint32_t sb = smem_to_u32(smem);

    const int tid = threadIdx.x;
    const int wid = tid >> 5, l = tid & 31;
    const int wm = wid & 1;            // n half (0/1): rows wm*32..+32
    const int wn = wid >> 1;           // h quarter (0..3): cols wn*32..+32
    const int b0 = blockIdx.y * 2;
    const int n0 = blockIdx.x * 64;

    // ---- Stage act for BOTH batches: LDG float4 -> half2 -> smem ----------
    const float4* g0 = (const float4*)(act + b0 * HDIM * HDIM);
    const float4* g1 = g0 + (HDIM * HDIM / 4);
    #pragma unroll
    for (int k = 0; k < 16; k++) {
        const int i = tid + k * 256;            // 0..4095 float4s
        const int r = i >> 5, q = i & 31;
        const float4 v0 = __ldg(&g0[i]);
        const float4 v1 = __ldg(&g1[i]);
        __half2* d0 = (__half2*)(smem + ACT0_OFF + r * NSTRIDE + q * 8);
        d0[0] = __floats2half2_rn(v0.x, v0.y);
        d0[1] = __floats2half2_rn(v0.z, v0.w);
        __half2* d1 = (__half2*)(smem + ACT1_OFF + r * NSTRIDE + q * 8);
        d1[0] = __floats2half2_rn(v1.x, v1.y);
        d1[1] = __floats2half2_rn(v1.z, v1.w);
    }

    // ---- EwT and Eh tiles, computed ONCE (32 exps/thread total) -----------
    {
        const int en = tid >> 2;                // table row (local n) 0..63
        const int qd = tid & 3;                 // 32-col quarter
        const float2 m = ((const float2*)mu)[n0 + en];
        const float2 s = ((const float2*)sigma)[n0 + en];
        const float invy = 1.0f / (2.0f * s.y * s.y);
        const float invx = 1.0f / (2.0f * s.x * s.x);
        char* rowW = smem + EW_OFF + en * NSTRIDE + qd * 64;
        char* rowH = smem + EH_OFF + en * NSTRIDE + qd * 64;
        const float j0 = (float)(qd * 32) * (1.0f / 128.0f);
        #pragma unroll
        for (int c4 = 0; c4 < 8; c4++) {
            float ew[4], eh[4];
            #pragma unroll
            for (int j = 0; j < 4; j++) {
                const float g = j0 + (float)(c4 * 4 + j) * (1.0f / 128.0f);
                const float dy = g - m.y;
                const float dx = g - m.x;
                ew[j] = __expf(-(dy * dy * invy));
                eh[j] = __expf(-(dx * dx * invx));
            }
            ((__half2*)(rowW + c4 * 8))[0] = __floats2half2_rn(ew[0], ew[1]);
            ((__half2*)(rowW + c4 * 8))[1] = __floats2half2_rn(ew[2], ew[3]);
            ((__half2*)(rowH + c4 * 8))[0] = __floats2half2_rn(eh[0], eh[1]);
            ((__half2*)(rowH + c4 * 8))[1] = __floats2half2_rn(eh[2], eh[3]);
        }
    }
    __syncthreads();

    // ---- Two batches: GEMM (M=64 N=128 K=128) + epilogue ------------------
    const uint32_t lrow = l & 15, lcol = (l >> 4) * 16;
    const uint32_t aBase = sb + EW_OFF + (wm * 32 + lrow) * NSTRIDE + lcol;
    float* red = (float*)(smem + RED_OFF);      // [4 wn][64 n]

    #pragma unroll
    for (int bb = 0; bb < 2; bb++) {
        const uint32_t bBase = sb + (bb ? ACT1_OFF : ACT0_OFF)
                             + (wn * 32 + lrow) * NSTRIDE + lcol;
        float acc[2][4][4];
        #pragma unroll
        for (int mt = 0; mt < 2; mt++)
            #pragma unroll
            for (int nt = 0; nt < 4; nt++)
                #pragma unroll
                for (int k = 0; k < 4; k++) acc[mt][nt][k] = 0.0f;

        #pragma unroll
        for (int ks = 0; ks < 8; ks++) {
            const uint32_t koff = ks * 32;
            uint32_t ah[2][4], bv[2][4];
            #pragma unroll
            for (int mt = 0; mt < 2; mt++)
                LDSM_X4(ah[mt][0], ah[mt][1], ah[mt][2], ah[mt][3],
                        aBase + mt * (16 * NSTRIDE) + koff);
            #pragma unroll
            for (int p = 0; p < 2; p++)
                LDSM_X4(bv[p][0], bv[p][1], bv[p][2], bv[p][3],
                        bBase + p * (16 * NSTRIDE) + koff);
            #pragma unroll
            for (int mt = 0; mt < 2; mt++)
                #pragma unroll
                for (int p = 0; p < 2; p++) {
                    MMA_F16(acc[mt][2 * p],     ah[mt], bv[p][0], bv[p][2]);
                    MMA_F16(acc[mt][2 * p + 1], ah[mt], bv[p][1], bv[p][3]);
                }
        }

        // Epilogue: D rows nloc = wm*32 + mt*16 + rh*8 + l/4,
        // cols h = wn*32 + nt*8 + 2(l&3)+{0,1}; Eh from smem (conflict-free).
        float rowsum[2][2];
        #pragma unroll
        for (int mt = 0; mt < 2; mt++)
            #pragma unroll
            for (int rh = 0; rh < 2; rh++) {
                const int nloc = wm * 32 + mt * 16 + rh * 8 + (l >> 2);
                const char* eRow = smem + EH_OFF + nloc * NSTRIDE
                                 + (wn * 32 + 2 * (l & 3)) * 2;
                float s = 0.0f;
                #pragma unroll
                for (int nt = 0; nt < 4; nt++) {
                    const float2 ef =
                        __half22float2(*(const __half2*)(eRow + nt * 16));
                    s += acc[mt][nt][rh * 2] * ef.x
                       + acc[mt][nt][rh * 2 + 1] * ef.y;
                }
                s += __shfl_xor_sync(0xFFFFFFFF, s, 1);
                s += __shfl_xor_sync(0xFFFFFFFF, s, 2);
                rowsum[mt][rh] = s;
            }

        __syncthreads();   // previous batch's red readers are done
        if ((l & 3) == 0) {
            #pragma unroll
            for (int mt = 0; mt < 2; mt++)
                #pragma unroll
                for (int rh = 0; rh < 2; rh++) {
                    const int nloc = wm * 32 + mt * 16 + rh * 8 + (l >> 2);
                    red[wn * 64 + nloc] = rowsum[mt][rh];
                }
        }
        __syncthreads();
        if (tid < 64)
            out[(b0 + bb) * NPTS + n0 + tid] =
                (red[tid] + red[64 + tid] + red[128 + tid] + red[192 + tid])
                * 6.103515625e-05f;   // 1/16384
    }
}

// ---------------------------------------------------------------------------
extern "C" void kernel_launch(void* const* d_in, const int* in_sizes, int n_in,
                              void* d_out, int out_size)
{
    const float* act   = (const float*)d_in[0];   // [8,128,128]
    const float* mu    = (const float*)d_in[1];   // [4096,2]
    const float* sigma = (const float*)d_in[2];   // [4096,2]
    float* out = (float*)d_out;                   // [8,64,64]

    cudaFuncSetAttribute(fused_kernel,
                         cudaFuncAttributeMaxDynamicSharedMemorySize, SMEM_REQ);

    fused_kernel<<<dim3(NPTS / 64, 4), 256, SMEM_REQ>>>(act, mu, sigma, out);
}

// round 11
// speedup vs baseline: 1.0049x; 1.0049x over previous
#include <cuda_runtime.h>
#include <cuda_fp16.h>
#include <cstdint>

// Fused kernel, small-CTA / high-occupancy variant:
// corr[b,n] = (1/16384) * sum_h Eh[n,h] * ( sum_w EwT[n,w] * act[b,h,w] )
// CTA = (n-tile 64, single batch): grid 512, 256 thr, 3 CTAs/SM (24 warps).
//   - EwT tile [64n x 128w] fp16 computed in-CTA (32 exps/thread)
//   - act tile [128h x 128w] fp32->fp16 staged in-CTA
//   - GEMM M=64 N=128 K=128 (mma.sync.m16n8k16.f16, fp32 accum)
//   - epilogue: Eh computed on the fly in fp32 (32 exps/thread)

#define HDIM 128
#define NPTS 4096

// Rows padded to 272B = 17*16 -> ldmatrix lane addrs conflict-free.
#define NSTRIDE  272
#define EW_OFF   0
#define ACT_OFF  17408                 // 64*272
#define MUX_OFF  52224                 // +128*272
#define INVX_OFF 52480
#define RED_OFF  52736                 // 4*64 floats
#define SMEM_REQ 53760

__device__ __forceinline__ uint32_t smem_to_u32(const void* p) {
    uint32_t a;
    asm("{ .reg .u64 t; cvta.to.shared.u64 t, %1; cvt.u32.u64 %0, t; }" : "=r"(a) : "l"(p));
    return a;
}

#define LDSM_X4(r0, r1, r2, r3, addr)                                          \
    asm volatile("ldmatrix.sync.aligned.m8n8.x4.shared.b16 {%0,%1,%2,%3}, [%4];" \
        : "=r"(r0), "=r"(r1), "=r"(r2), "=r"(r3) : "r"(addr))

#define MMA_F16(c, a, b0, b1)                                                  \
    asm volatile("mma.sync.aligned.m16n8k16.row.col.f32.f16.f16.f32 "           \
        "{%0,%1,%2,%3},{%4,%5,%6,%7},{%8,%9},{%0,%1,%2,%3};"                    \
        : "+f"((c)[0]), "+f"((c)[1]), "+f"((c)[2]), "+f"((c)[3])                \
        : "r"((a)[0]), "r"((a)[1]), "r"((a)[2]), "r"((a)[3]), "r"(b0), "r"(b1))

__global__ __launch_bounds__(256, 3) void fused_kernel(
    const float* __restrict__ act,    // [8,128,128]
    const float* __restrict__ mu,     // [4096,2]
    const float* __restrict__ sigma,  // [4096,2]
    float* __restrict__ out)          // [8,4096]
{
    extern __shared__ char smem[];
    const uint32_t sb = smem_to_u32(smem);

    const int tid = threadIdx.x;
    const int wid = tid >> 5, l = tid & 31;
    const int wm = wid & 1;            // n half: rows wm*32..+32
    const int wn = wid >> 1;           // h quarter: cols wn*32..+32
    const int b  = blockIdx.y;
    const int n0 = blockIdx.x * 64;

    // ---- EwT tile + mux/invx cache (issue mu/sigma LDG first) -------------
    const int en = tid >> 2;                    // table row (local n) 0..63
    const int qd = tid & 3;                     // 32-col quarter
    const float2 m = ((const float2*)mu)[n0 + en];
    const float2 s = ((const float2*)sigma)[n0 + en];

    // ---- Stage act: LDG float4 -> half2 -> smem (overlaps with exps) ------
    const float4* gact = (const float4*)(act + b * HDIM * HDIM);
    #pragma unroll
    for (int k = 0; k < 16; k++) {
        const int i = tid + k * 256;            // 0..4095 float4s
        const int r = i >> 5, q = i & 31;
        const float4 v = __ldg(&gact[i]);
        __half2* dst = (__half2*)(smem + ACT_OFF + r * NSTRIDE + q * 8);
        dst[0] = __floats2half2_rn(v.x, v.y);
        dst[1] = __floats2half2_rn(v.z, v.w);
    }

    {
        const float invy = 1.0f / (2.0f * s.y * s.y);
        const float invx = 1.0f / (2.0f * s.x * s.x);
        if (qd == 0) {
            *(float*)(smem + MUX_OFF + en * 4)  = m.x;
            *(float*)(smem + INVX_OFF + en * 4) = invx;
        }
        char* rowW = smem + EW_OFF + en * NSTRIDE + qd * 64;
        const float j0 = (float)(qd * 32) * (1.0f / 128.0f);
        #pragma unroll
        for (int c4 = 0; c4 < 8; c4++) {
            float ew[4];
            #pragma unroll
            for (int j = 0; j < 4; j++) {
                const float dy =
                    j0 + (float)(c4 * 4 + j) * (1.0f / 128.0f) - m.y;
                ew[j] = __expf(-(dy * dy * invy));
            }
            ((__half2*)(rowW + c4 * 8))[0] = __floats2half2_rn(ew[0], ew[1]);
            ((__half2*)(rowW + c4 * 8))[1] = __floats2half2_rn(ew[2], ew[3]);
        }
    }
    __syncthreads();

    // ---- GEMM: M=64 N=128 K=128, warp tile 32n x 32h ----------------------
    const uint32_t lrow = l & 15, lcol = (l >> 4) * 16;
    const uint32_t aBase = sb + EW_OFF + (wm * 32 + lrow) * NSTRIDE + lcol;
    const uint32_t bBase = sb + ACT_OFF + (wn * 32 + lrow) * NSTRIDE + lcol;

    float acc[2][4][4];
    #pragma unroll
    for (int mt = 0; mt < 2; mt++)
        #pragma unroll
        for (int nt = 0; nt < 4; nt++)
            #pragma unroll
            for (int k = 0; k < 4; k++) acc[mt][nt][k] = 0.0f;

    #pragma unroll
    for (int ks = 0; ks < 8; ks++) {
        const uint32_t koff = ks * 32;
        uint32_t ah[2][4], bv[2][4];
        #pragma unroll
        for (int mt = 0; mt < 2; mt++)
            LDSM_X4(ah[mt][0], ah[mt][1], ah[mt][2], ah[mt][3],
                    aBase + mt * (16 * NSTRIDE) + koff);
        #pragma unroll
        for (int p = 0; p < 2; p++)
            LDSM_X4(bv[p][0], bv[p][1], bv[p][2], bv[p][3],
                    bBase + p * (16 * NSTRIDE) + koff);
        #pragma unroll
        for (int mt = 0; mt < 2; mt++)
            #pragma unroll
            for (int p = 0; p < 2; p++) {
                MMA_F16(acc[mt][2 * p],     ah[mt], bv[p][0], bv[p][2]);
                MMA_F16(acc[mt][2 * p + 1], ah[mt], bv[p][1], bv[p][3]);
            }
    }

    // ---- Epilogue: Eh on the fly (fp32), quad shuffle, smem reduce --------
    // D rows: nloc = wm*32 + mt*16 + rh*8 + l/4; cols h = wn*32 + nt*8 + 2(l&3)+{0,1}
    const float h0f = (float)(wn * 32 + 2 * (l & 3)) * (1.0f / 128.0f);
    float rowsum[2][2];
    #pragma unroll
    for (int mt = 0; mt < 2; mt++)
        #pragma unroll
        for (int rh = 0; rh < 2; rh++) {
            const int nloc = wm * 32 + mt * 16 + rh * 8 + (l >> 2);
            const float a   = *(const float*)(smem + MUX_OFF + nloc * 4);
            const float inv = *(const float*)(smem + INVX_OFF + nloc * 4);
            float sum = 0.0f;
            #pragma unroll
            for (int nt = 0; nt < 4; nt++) {
                const float d0 = h0f + (float)nt * (8.0f / 128.0f) - a;
                const float d1 = d0 + (1.0f / 128.0f);
                const float e0 = __expf(-(d0 * d0 * inv));
                const float e1 = __expf(-(d1 * d1 * inv));
                sum += acc[mt][nt][rh * 2] * e0 + acc[mt][nt][rh * 2 + 1] * e1;
            }
            sum += __shfl_xor_sync(0xFFFFFFFF, sum, 1);
            sum += __shfl_xor_sync(0xFFFFFFFF, sum, 2);
            rowsum[mt][rh] = sum;
        }

    float* red = (float*)(smem + RED_OFF);      // [4 wn][64 n]
    if ((l & 3) == 0) {
        #pragma unroll
        for (int mt = 0; mt < 2; mt++)
            #pragma unroll
            for (int rh = 0; rh < 2; rh++) {
                const int nloc = wm * 32 + mt * 16 + rh * 8 + (l >> 2);
                red[wn * 64 + nloc] = rowsum[mt][rh];
            }
    }
    __syncthreads();
    if (tid < 64)
        out[b * NPTS + n0 + tid] =
            (red[tid] + red[64 + tid] + red[128 + tid] + red[192 + tid])
            * 6.103515625e-05f;   // 1/16384
}

// ---------------------------------------------------------------------------
extern "C" void kernel_launch(void* const* d_in, const int* in_sizes, int n_in,
                              void* d_out, int out_size)
{
    const float* act   = (const float*)d_in[0];   // [8,128,128]
    const float* mu    = (const float*)d_in[1];   // [4096,2]
    const float* sigma = (const float*)d_in[2];   // [4096,2]
    float* out = (float*)d_out;                   // [8,64,64]

    cudaFuncSetAttribute(fused_kernel,
                         cudaFuncAttributeMaxDynamicSharedMemorySize, SMEM_REQ);

    fused_kernel<<<dim3(NPTS / 64, 8), 256, SMEM_REQ>>>(act, mu, sigma, out);
}